// round 16
// baseline (speedup 1.0000x reference)
#include <cuda_runtime.h>
#include <cuda_fp16.h>
#include <cstdint>

#define OMEGA0 30.0f
#define BLK 128
#define MAXCTAS 1036   // 148 SMs x 7 CTAs

// ---------------- helpers ----------------
__device__ __forceinline__ float fast_sigmoid(float t) {
    return __fdividef(1.0f, 1.0f + __expf(-t));
}
__device__ __forceinline__ uint32_t pack_f16x2(float x, float y) {
    uint32_t r;
    asm("cvt.rn.f16x2.f32 %0, %1, %2;" : "=r"(r) : "f"(y), "f"(x));
    return r;
}
// D += A * B
__device__ __forceinline__ void mma_f16(float d[4], const uint32_t a[4],
                                        uint32_t b0, uint32_t b1) {
    asm volatile(
        "mma.sync.aligned.m16n8k16.row.col.f32.f16.f16.f32 "
        "{%0,%1,%2,%3}, {%4,%5,%6,%7}, {%8,%9}, {%0,%1,%2,%3};"
        : "+f"(d[0]), "+f"(d[1]), "+f"(d[2]), "+f"(d[3])
        : "r"(a[0]), "r"(a[1]), "r"(a[2]), "r"(a[3]), "r"(b0), "r"(b1));
}
// D = A * B + {c0,c1,c0,c1}
__device__ __forceinline__ void mma_f16_bias(float d[4], const uint32_t a[4],
                                             uint32_t b0, uint32_t b1,
                                             float c0, float c1) {
    asm volatile(
        "mma.sync.aligned.m16n8k16.row.col.f32.f16.f16.f32 "
        "{%0,%1,%2,%3}, {%4,%5,%6,%7}, {%8,%9}, {%10,%11,%10,%11};"
        : "=f"(d[0]), "=f"(d[1]), "=f"(d[2]), "=f"(d[3])
        : "r"(a[0]), "r"(a[1]), "r"(a[2]), "r"(a[3]), "r"(b0), "r"(b1),
          "f"(c0), "f"(c1));
}

// one mid layer: Ain (A fragments) -> Aout (A fragments), sines fused with pack
#define MID_LAYER(Ain, Aout, Lc) do {                                          \
    uint32_t B_[16];                                                           \
    {                                                                          \
        const uint4* bp_ = (const uint4*)&fragMid[Lc][lane][0];                \
        uint4 q0_ = bp_[0], q1_ = bp_[1], q2_ = bp_[2], q3_ = bp_[3];          \
        B_[0]=q0_.x; B_[1]=q0_.y; B_[2]=q0_.z; B_[3]=q0_.w;                    \
        B_[4]=q1_.x; B_[5]=q1_.y; B_[6]=q1_.z; B_[7]=q1_.w;                    \
        B_[8]=q2_.x; B_[9]=q2_.y; B_[10]=q2_.z; B_[11]=q2_.w;                  \
        B_[12]=q3_.x; B_[13]=q3_.y; B_[14]=q3_.z; B_[15]=q3_.w;                \
    }                                                                          \
    _Pragma("unroll")                                                          \
    for (int nt_ = 0; nt_ < 4; nt_++) {                                        \
        float2 bb_ = biasM[Lc][nt_ * 4 + t4];                                  \
        _Pragma("unroll")                                                      \
        for (int mt_ = 0; mt_ < 2; mt_++) {                                    \
            float d_[4];                                                       \
            mma_f16_bias(d_, Ain[mt_][0], B_[nt_], B_[4 + nt_], bb_.x, bb_.y); \
            mma_f16     (d_, Ain[mt_][1], B_[8 + nt_], B_[12 + nt_]);          \
            d_[0] = __sinf(d_[0]); d_[1] = __sinf(d_[1]);                      \
            d_[2] = __sinf(d_[2]); d_[3] = __sinf(d_[3]);                      \
            Aout[mt_][nt_ >> 1][2 * (nt_ & 1)]     = pack_f16x2(d_[0], d_[1]); \
            Aout[mt_][nt_ >> 1][2 * (nt_ & 1) + 1] = pack_f16x2(d_[2], d_[3]); \
        }                                                                      \
    }                                                                          \
} while (0)

__global__ void __launch_bounds__(BLK, 7)
siren_hmma(const float* __restrict__ coords,
           const float* __restrict__ w0g, const float* __restrict__ b0g,
           const float* __restrict__ w1g, const float* __restrict__ b1g,
           const float* __restrict__ w2g, const float* __restrict__ b2g,
           const float* __restrict__ w3g, const float* __restrict__ b3g,
           const float* __restrict__ w4g, const float* __restrict__ b4g,
           const float* __restrict__ w5g, const float* __restrict__ b5g,
           const float* __restrict__ wfg, const float* __restrict__ bfg,
           float* __restrict__ out, int numPts, int numTiles)
{
    __shared__ __align__(16) uint32_t fragMid[4][32][20];
    __shared__ __align__(16) uint32_t frag5[32][12];
    __shared__ float2 biasM[4][16];
    __shared__ float2 bias5[8];
    // L0 packed: per (nt,t4): w cols (2t4, 2t4+1) of rows nt*8.. as float4 + bias float2
    __shared__ __align__(16) float4 s_w0p[16];
    __shared__ float2 s_b0p[16];
    __shared__ float s_wf[48], s_bf[3];

    const int tid = threadIdx.x;
    const int lane = tid & 31, wid = tid >> 5;
    const int t4 = lane & 3, g = lane >> 2;

    // ---- fill weight fragments ----
#define FILL_MID(Lc, WP)                                                       \
    for (int e = tid; e < 512; e += BLK) {                                     \
        int q = e >> 5, ln = e & 31;                                           \
        int tt = ln & 3, gg = ln >> 2;                                         \
        int kt = q >> 3, r = (q >> 2) & 1, nt = q & 3;                         \
        int k0 = kt * 16 + r * 8 + tt * 2;                                     \
        int n  = nt * 8 + gg;                                                  \
        fragMid[Lc][ln][q] = pack_f16x2(OMEGA0 * WP[n * 32 + k0],              \
                                        OMEGA0 * WP[n * 32 + k0 + 1]);         \
    }
    FILL_MID(0, w1g) FILL_MID(1, w2g) FILL_MID(2, w3g) FILL_MID(3, w4g)
#undef FILL_MID

    for (int e = tid; e < 256; e += BLK) {
        int q = e >> 5, ln = e & 31;
        int tt = ln & 3, gg = ln >> 2;
        int kt = q >> 2, r = (q >> 1) & 1, nt = q & 1;
        int k0 = kt * 16 + r * 8 + tt * 2;
        int n  = nt * 8 + gg;
        frag5[ln][q] = pack_f16x2(OMEGA0 * w5g[n * 32 + k0],
                                  OMEGA0 * w5g[n * 32 + k0 + 1]);
    }
#define FILL_BIAS(Lc, BP)                                                      \
    if (tid < 16) {                                                            \
        int nt = tid >> 2, tt = tid & 3;                                       \
        biasM[Lc][tid] = make_float2(OMEGA0 * BP[nt * 8 + tt * 2],             \
                                     OMEGA0 * BP[nt * 8 + tt * 2 + 1]);        \
    }
    FILL_BIAS(0, b1g) FILL_BIAS(1, b2g) FILL_BIAS(2, b3g) FILL_BIAS(3, b4g)
#undef FILL_BIAS
    if (tid < 8) {
        int nt = tid >> 2, tt = tid & 3;
        bias5[tid] = make_float2(OMEGA0 * b5g[nt * 8 + tt * 2],
                                 OMEGA0 * b5g[nt * 8 + tt * 2 + 1]);
    }
    // L0 packed weights/biases: index = nt*4 + t4, col = nt*8 + t4*2
    if (tid < 16) {
        int nt = tid >> 2, tt = tid & 3;
        int col = nt * 8 + tt * 2;
        s_w0p[tid] = make_float4(OMEGA0 * w0g[2 * col],     OMEGA0 * w0g[2 * col + 1],
                                 OMEGA0 * w0g[2 * col + 2], OMEGA0 * w0g[2 * col + 3]);
        s_b0p[tid] = make_float2(OMEGA0 * b0g[col], OMEGA0 * b0g[col + 1]);
    }
    if (tid < 48) s_wf[tid] = wfg[tid];
    if (tid < 3)  s_bf[tid] = bfg[tid];
    __syncthreads();

    // ---------------- main loop: 128 points per CTA-iter (32 per warp) ----------------
#pragma unroll 1
    for (int tile = blockIdx.x; tile < numTiles; tile += gridDim.x) {
        const int pbase = tile * 128 + wid * 32;

        uint32_t A0[2][2][4], A1[2][2][4];   // activations as packed A-fragments

        // ---- layer 0: 2 -> 32 scalar, hoisted packed weights, packed into A0 ----
        {
            float4 W0[4]; float2 B0[4];
#pragma unroll
            for (int nt = 0; nt < 4; nt++) {
                W0[nt] = s_w0p[nt * 4 + t4];
                B0[nt] = s_b0p[nt * 4 + t4];
            }
#pragma unroll
            for (int mt = 0; mt < 2; mt++) {
                int p0 = pbase + mt * 16 + g;
                float2 c0 = (p0 < numPts)     ? ((const float2*)coords)[p0]     : make_float2(0.f, 0.f);
                float2 c1 = (p0 + 8 < numPts) ? ((const float2*)coords)[p0 + 8] : make_float2(0.f, 0.f);
#pragma unroll
                for (int nt = 0; nt < 4; nt++) {
                    float d0 = __sinf(fmaf(c0.x, W0[nt].x, fmaf(c0.y, W0[nt].y, B0[nt].x)));
                    float d1 = __sinf(fmaf(c0.x, W0[nt].z, fmaf(c0.y, W0[nt].w, B0[nt].y)));
                    float d2 = __sinf(fmaf(c1.x, W0[nt].x, fmaf(c1.y, W0[nt].y, B0[nt].x)));
                    float d3 = __sinf(fmaf(c1.x, W0[nt].z, fmaf(c1.y, W0[nt].w, B0[nt].y)));
                    A0[mt][nt >> 1][2 * (nt & 1)]     = pack_f16x2(d0, d1);
                    A0[mt][nt >> 1][2 * (nt & 1) + 1] = pack_f16x2(d2, d3);
                }
            }
        }

        // ---- 4 middle layers, ping-pong fragment arrays ----
        MID_LAYER(A0, A1, 0);
        MID_LAYER(A1, A0, 1);
        MID_LAYER(A0, A1, 2);
        MID_LAYER(A1, A0, 3);

        // ---- layer 5: 32 -> 16, output kept as f32 z ----
        float z[2][2][4];
        {
            uint32_t B5[8];
            {
                const uint4* bp = (const uint4*)&frag5[lane][0];
                uint4 b0_ = bp[0], b1_ = bp[1];
                B5[0]=b0_.x; B5[1]=b0_.y; B5[2]=b0_.z; B5[3]=b0_.w;
                B5[4]=b1_.x; B5[5]=b1_.y; B5[6]=b1_.z; B5[7]=b1_.w;
            }
#pragma unroll
            for (int nt = 0; nt < 2; nt++) {
                float2 bb = bias5[nt * 4 + t4];
#pragma unroll
                for (int mt = 0; mt < 2; mt++) {
                    mma_f16_bias(z[mt][nt], A0[mt][0], B5[nt], B5[2 + nt], bb.x, bb.y);
                    mma_f16     (z[mt][nt], A0[mt][1], B5[4 + nt], B5[6 + nt]);
#pragma unroll
                    for (int i = 0; i < 4; i++)
                        z[mt][nt][i] = __sinf(z[mt][nt][i]);
                }
            }
        }

        // ---- final 16 -> 3 + sigmoid: per-lane partials + butterfly reduce ----
#pragma unroll
        for (int mt = 0; mt < 2; mt++) {
            float s[2][3];
#pragma unroll
            for (int c = 0; c < 3; c++) {
                float2 wa = ((const float2*)s_wf)[c * 8 + t4];
                float2 wb = ((const float2*)s_wf)[c * 8 + 4 + t4];
#pragma unroll
                for (int r = 0; r < 2; r++) {
                    float acc = z[mt][0][2 * r]     * wa.x
                              + z[mt][0][2 * r + 1] * wa.y
                              + z[mt][1][2 * r]     * wb.x
                              + z[mt][1][2 * r + 1] * wb.y;
                    acc += __shfl_xor_sync(0xffffffffu, acc, 1);
                    acc += __shfl_xor_sync(0xffffffffu, acc, 2);
                    s[r][c] = acc + s_bf[c];
                }
            }
            if (t4 < 3) {
#pragma unroll
                for (int r = 0; r < 2; r++) {
                    int p = pbase + mt * 16 + g + 8 * r;
                    if (p < numPts) {
                        float val = (t4 == 0) ? s[r][0] : ((t4 == 1) ? s[r][1] : s[r][2]);
                        out[(size_t)p * 3 + t4] = fast_sigmoid(val);
                    }
                }
            }
        }
    }
}

extern "C" void kernel_launch(void* const* d_in, const int* in_sizes, int n_in,
                              void* d_out, int out_size)
{
    const float* coords = (const float*)d_in[0];
    const float* w0 = (const float*)d_in[1];  const float* b0 = (const float*)d_in[2];
    const float* w1 = (const float*)d_in[3];  const float* b1 = (const float*)d_in[4];
    const float* w2 = (const float*)d_in[5];  const float* b2 = (const float*)d_in[6];
    const float* w3 = (const float*)d_in[7];  const float* b3 = (const float*)d_in[8];
    const float* w4 = (const float*)d_in[9];  const float* b4 = (const float*)d_in[10];
    const float* w5 = (const float*)d_in[11]; const float* b5 = (const float*)d_in[12];
    const float* wf = (const float*)d_in[13]; const float* bf = (const float*)d_in[14];

    int numPts = in_sizes[0] / 2;
    int numTiles = (numPts + 127) / 128;
    int grid = numTiles < MAXCTAS ? numTiles : MAXCTAS;

    siren_hmma<<<grid, BLK>>>(coords, w0, b0, w1, b1, w2, b2, w3, b3, w4, b4,
                              w5, b5, wf, bf, (float*)d_out, numPts, numTiles);
}

// round 17
// speedup vs baseline: 1.0370x; 1.0370x over previous
#include <cuda_runtime.h>
#include <cuda_fp16.h>
#include <cstdint>

#define OMEGA0 30.0f
#define BLK 128
#define MAXCTAS 1036   // 148 SMs x 7 CTAs

// ---------------- helpers ----------------
__device__ __forceinline__ float fast_sigmoid(float t) {
    return __fdividef(1.0f, 1.0f + __expf(-t));
}
__device__ __forceinline__ uint32_t pack_f16x2(float x, float y) {
    uint32_t r;
    asm("cvt.rn.f16x2.f32 %0, %1, %2;" : "=r"(r) : "f"(y), "f"(x));
    return r;
}
__device__ __forceinline__ uint32_t smem_u32(const void* p) {
    uint32_t a;
    asm("{ .reg .u64 t; cvta.to.shared.u64 t, %1; cvt.u32.u64 %0, t; }" : "=r"(a) : "l"(p));
    return a;
}
// D += A * B
__device__ __forceinline__ void mma_f16(float d[4], const uint32_t a[4],
                                        uint32_t b0, uint32_t b1) {
    asm volatile(
        "mma.sync.aligned.m16n8k16.row.col.f32.f16.f16.f32 "
        "{%0,%1,%2,%3}, {%4,%5,%6,%7}, {%8,%9}, {%0,%1,%2,%3};"
        : "+f"(d[0]), "+f"(d[1]), "+f"(d[2]), "+f"(d[3])
        : "r"(a[0]), "r"(a[1]), "r"(a[2]), "r"(a[3]), "r"(b0), "r"(b1));
}
// D = A * B + {c0,c1,c0,c1}
__device__ __forceinline__ void mma_f16_bias(float d[4], const uint32_t a[4],
                                             uint32_t b0, uint32_t b1,
                                             float c0, float c1) {
    asm volatile(
        "mma.sync.aligned.m16n8k16.row.col.f32.f16.f16.f32 "
        "{%0,%1,%2,%3}, {%4,%5,%6,%7}, {%8,%9}, {%10,%11,%10,%11};"
        : "=f"(d[0]), "=f"(d[1]), "=f"(d[2]), "=f"(d[3])
        : "r"(a[0]), "r"(a[1]), "r"(a[2]), "r"(a[3]), "r"(b0), "r"(b1),
          "f"(c0), "f"(c1));
}

// one mid layer: Ain (A fragments) -> Aout (A fragments), sines fused with pack
#define MID_LAYER(Ain, Aout, Lc) do {                                          \
    uint32_t B_[16];                                                           \
    {                                                                          \
        const uint4* bp_ = (const uint4*)&fragMid[Lc][lane][0];                \
        uint4 q0_ = bp_[0], q1_ = bp_[1], q2_ = bp_[2], q3_ = bp_[3];          \
        B_[0]=q0_.x; B_[1]=q0_.y; B_[2]=q0_.z; B_[3]=q0_.w;                    \
        B_[4]=q1_.x; B_[5]=q1_.y; B_[6]=q1_.z; B_[7]=q1_.w;                    \
        B_[8]=q2_.x; B_[9]=q2_.y; B_[10]=q2_.z; B_[11]=q2_.w;                  \
        B_[12]=q3_.x; B_[13]=q3_.y; B_[14]=q3_.z; B_[15]=q3_.w;                \
    }                                                                          \
    _Pragma("unroll")                                                          \
    for (int nt_ = 0; nt_ < 4; nt_++) {                                        \
        float2 bb_ = biasM[Lc][nt_ * 4 + t4];                                  \
        _Pragma("unroll")                                                      \
        for (int mt_ = 0; mt_ < 2; mt_++) {                                    \
            float d_[4];                                                       \
            mma_f16_bias(d_, Ain[mt_][0], B_[nt_], B_[4 + nt_], bb_.x, bb_.y); \
            mma_f16     (d_, Ain[mt_][1], B_[8 + nt_], B_[12 + nt_]);          \
            d_[0] = __sinf(d_[0]); d_[1] = __sinf(d_[1]);                      \
            d_[2] = __sinf(d_[2]); d_[3] = __sinf(d_[3]);                      \
            Aout[mt_][nt_ >> 1][2 * (nt_ & 1)]     = pack_f16x2(d_[0], d_[1]); \
            Aout[mt_][nt_ >> 1][2 * (nt_ & 1) + 1] = pack_f16x2(d_[2], d_[3]); \
        }                                                                      \
    }                                                                          \
} while (0)

__global__ void __launch_bounds__(BLK, 7)
siren_hmma(const float* __restrict__ coords,
           const float* __restrict__ w0g, const float* __restrict__ b0g,
           const float* __restrict__ w1g, const float* __restrict__ b1g,
           const float* __restrict__ w2g, const float* __restrict__ b2g,
           const float* __restrict__ w3g, const float* __restrict__ b3g,
           const float* __restrict__ w4g, const float* __restrict__ b4g,
           const float* __restrict__ w5g, const float* __restrict__ b5g,
           const float* __restrict__ wfg, const float* __restrict__ bfg,
           float* __restrict__ out, int numPts, int numTiles)
{
    __shared__ __align__(16) uint32_t fragMid[4][32][20];
    __shared__ __align__(16) uint32_t frag5[32][12];
    __shared__ float2 biasM[4][16];
    __shared__ float2 bias5[8];
    __shared__ float s_w0[64], s_b0[32], s_wf[48], s_bf[3];
    __shared__ __align__(16) float2 cbuf[2][BLK];   // double-buffered coords

    const int tid = threadIdx.x;
    const int lane = tid & 31, wid = tid >> 5;
    const int t4 = lane & 3, g = lane >> 2;

    // ---- fill weight fragments ----
#define FILL_MID(Lc, WP)                                                       \
    for (int e = tid; e < 512; e += BLK) {                                     \
        int q = e >> 5, ln = e & 31;                                           \
        int tt = ln & 3, gg = ln >> 2;                                         \
        int kt = q >> 3, r = (q >> 2) & 1, nt = q & 3;                         \
        int k0 = kt * 16 + r * 8 + tt * 2;                                     \
        int n  = nt * 8 + gg;                                                  \
        fragMid[Lc][ln][q] = pack_f16x2(OMEGA0 * WP[n * 32 + k0],              \
                                        OMEGA0 * WP[n * 32 + k0 + 1]);         \
    }
    FILL_MID(0, w1g) FILL_MID(1, w2g) FILL_MID(2, w3g) FILL_MID(3, w4g)
#undef FILL_MID

    for (int e = tid; e < 256; e += BLK) {
        int q = e >> 5, ln = e & 31;
        int tt = ln & 3, gg = ln >> 2;
        int kt = q >> 2, r = (q >> 1) & 1, nt = q & 1;
        int k0 = kt * 16 + r * 8 + tt * 2;
        int n  = nt * 8 + gg;
        frag5[ln][q] = pack_f16x2(OMEGA0 * w5g[n * 32 + k0],
                                  OMEGA0 * w5g[n * 32 + k0 + 1]);
    }
#define FILL_BIAS(Lc, BP)                                                      \
    if (tid < 16) {                                                            \
        int nt = tid >> 2, tt = tid & 3;                                       \
        biasM[Lc][tid] = make_float2(OMEGA0 * BP[nt * 8 + tt * 2],             \
                                     OMEGA0 * BP[nt * 8 + tt * 2 + 1]);        \
    }
    FILL_BIAS(0, b1g) FILL_BIAS(1, b2g) FILL_BIAS(2, b3g) FILL_BIAS(3, b4g)
#undef FILL_BIAS
    if (tid < 8) {
        int nt = tid >> 2, tt = tid & 3;
        bias5[tid] = make_float2(OMEGA0 * b5g[nt * 8 + tt * 2],
                                 OMEGA0 * b5g[nt * 8 + tt * 2 + 1]);
    }
    if (tid < 64) s_w0[tid] = OMEGA0 * w0g[tid];
    if (tid < 32) s_b0[tid] = OMEGA0 * b0g[tid];
    if (tid < 48) s_wf[tid] = wfg[tid];
    if (tid < 3)  s_bf[tid] = bfg[tid];
    __syncthreads();

    const int lastPt = numPts - 1;
    // warp-private prefetch of one tile's coords for this warp (8 B per thread)
    const uint32_t myslot0 = smem_u32(&cbuf[0][wid * 32 + lane]);
    const uint32_t myslot1 = smem_u32(&cbuf[1][wid * 32 + lane]);

#define PREFETCH(tile_, slot_) do {                                            \
    int p_ = (tile_) * 128 + wid * 32 + lane;                                  \
    p_ = p_ < lastPt ? p_ : lastPt;                                            \
    const float2* gp_ = (const float2*)coords + p_;                            \
    asm volatile("cp.async.ca.shared.global [%0], [%1], 8;"                    \
                 :: "r"(slot_), "l"(gp_) : "memory");                          \
    asm volatile("cp.async.commit_group;" ::: "memory");                       \
} while (0)

    // prologue: fetch first tile
    PREFETCH(blockIdx.x, myslot0);
    asm volatile("cp.async.wait_group 0;" ::: "memory");

    int buf = 0;

    // ---------------- main loop: 128 points per CTA-iter (32 per warp) ----------------
#pragma unroll 1
    for (int tile = blockIdx.x; tile < numTiles; tile += gridDim.x) {
        const int pbase = tile * 128 + wid * 32;

        // kick off next tile's coords fetch into the other buffer (warp-private)
        {
            int nxt = tile + gridDim.x;
            if (nxt < numTiles) PREFETCH(nxt, buf ? myslot0 : myslot1);
        }

        uint32_t A0[2][2][4], A1[2][2][4];   // activations as packed A-fragments

        // ---- layer 0: 2 -> 32 scalar from smem coords, packed into A0 ----
        const float2* cw = &cbuf[buf][wid * 32];
#pragma unroll
        for (int mt = 0; mt < 2; mt++) {
            float2 c0 = cw[mt * 16 + g];
            float2 c1 = cw[mt * 16 + g + 8];
#pragma unroll
            for (int nt = 0; nt < 4; nt++) {
                int col = nt * 8 + t4 * 2;
                float2 wa = ((const float2*)s_w0)[col];
                float2 wb = ((const float2*)s_w0)[col + 1];
                float ba = s_b0[col], bb_ = s_b0[col + 1];
                float d0 = __sinf(fmaf(c0.x, wa.x, fmaf(c0.y, wa.y, ba)));
                float d1 = __sinf(fmaf(c0.x, wb.x, fmaf(c0.y, wb.y, bb_)));
                float d2 = __sinf(fmaf(c1.x, wa.x, fmaf(c1.y, wa.y, ba)));
                float d3 = __sinf(fmaf(c1.x, wb.x, fmaf(c1.y, wb.y, bb_)));
                A0[mt][nt >> 1][2 * (nt & 1)]     = pack_f16x2(d0, d1);
                A0[mt][nt >> 1][2 * (nt & 1) + 1] = pack_f16x2(d2, d3);
            }
        }

        // ---- 4 middle layers, ping-pong fragment arrays ----
        MID_LAYER(A0, A1, 0);
        MID_LAYER(A1, A0, 1);
        MID_LAYER(A0, A1, 2);
        MID_LAYER(A1, A0, 3);

        // ---- layer 5: 32 -> 16, output kept as f32 z ----
        float z[2][2][4];
        {
            uint32_t B5[8];
            {
                const uint4* bp = (const uint4*)&frag5[lane][0];
                uint4 b0_ = bp[0], b1_ = bp[1];
                B5[0]=b0_.x; B5[1]=b0_.y; B5[2]=b0_.z; B5[3]=b0_.w;
                B5[4]=b1_.x; B5[5]=b1_.y; B5[6]=b1_.z; B5[7]=b1_.w;
            }
#pragma unroll
            for (int nt = 0; nt < 2; nt++) {
                float2 bb = bias5[nt * 4 + t4];
#pragma unroll
                for (int mt = 0; mt < 2; mt++) {
                    mma_f16_bias(z[mt][nt], A0[mt][0], B5[nt], B5[2 + nt], bb.x, bb.y);
                    mma_f16     (z[mt][nt], A0[mt][1], B5[4 + nt], B5[6 + nt]);
#pragma unroll
                    for (int i = 0; i < 4; i++)
                        z[mt][nt][i] = __sinf(z[mt][nt][i]);
                }
            }
        }

        // ---- final 16 -> 3 + sigmoid: per-lane partials + butterfly reduce ----
#pragma unroll
        for (int mt = 0; mt < 2; mt++) {
            float s[2][3];
#pragma unroll
            for (int c = 0; c < 3; c++) {
                float2 wa = ((const float2*)s_wf)[c * 8 + t4];
                float2 wb = ((const float2*)s_wf)[c * 8 + 4 + t4];
#pragma unroll
                for (int r = 0; r < 2; r++) {
                    float acc = z[mt][0][2 * r]     * wa.x
                              + z[mt][0][2 * r + 1] * wa.y
                              + z[mt][1][2 * r]     * wb.x
                              + z[mt][1][2 * r + 1] * wb.y;
                    acc += __shfl_xor_sync(0xffffffffu, acc, 1);
                    acc += __shfl_xor_sync(0xffffffffu, acc, 2);
                    s[r][c] = acc + s_bf[c];
                }
            }
            if (t4 < 3) {
#pragma unroll
                for (int r = 0; r < 2; r++) {
                    int p = pbase + mt * 16 + g + 8 * r;
                    if (p < numPts) {
                        float val = (t4 == 0) ? s[r][0] : ((t4 == 1) ? s[r][1] : s[r][2]);
                        out[(size_t)p * 3 + t4] = fast_sigmoid(val);
                    }
                }
            }
        }

        // drain this warp's outstanding prefetch, flip buffers
        asm volatile("cp.async.wait_group 0;" ::: "memory");
        buf ^= 1;
    }
}

extern "C" void kernel_launch(void* const* d_in, const int* in_sizes, int n_in,
                              void* d_out, int out_size)
{
    const float* coords = (const float*)d_in[0];
    const float* w0 = (const float*)d_in[1];  const float* b0 = (const float*)d_in[2];
    const float* w1 = (const float*)d_in[3];  const float* b1 = (const float*)d_in[4];
    const float* w2 = (const float*)d_in[5];  const float* b2 = (const float*)d_in[6];
    const float* w3 = (const float*)d_in[7];  const float* b3 = (const float*)d_in[8];
    const float* w4 = (const float*)d_in[9];  const float* b4 = (const float*)d_in[10];
    const float* w5 = (const float*)d_in[11]; const float* b5 = (const float*)d_in[12];
    const float* wf = (const float*)d_in[13]; const float* bf = (const float*)d_in[14];

    int numPts = in_sizes[0] / 2;
    int numTiles = (numPts + 127) / 128;
    int grid = numTiles < MAXCTAS ? numTiles : MAXCTAS;

    siren_hmma<<<grid, BLK>>>(coords, w0, b0, w1, b1, w2, b2, w3, b3, w4, b4,
                              w5, b5, wf, bf, (float*)d_out, numPts, numTiles);
}